// round 1
// baseline (speedup 1.0000x reference)
#include <cuda_runtime.h>
#include <cuda_bf16.h>

// Problem constants
#define BB   16
#define CIN  1024
#define TT   2000
#define BNC  512
#define OUTC 512
#define NBR  3
#define FSZ  (BB * OUTC * TT)          // 16,384,000 elements per branch

// Scratch (device globals: allocation-guard-safe)
__device__ float g_h2[BB * BNC * TT];          // 65.5 MB
__device__ float g_f[NBR * FSZ];               // 196.6 MB
__device__ float g_stats[BB * 4 * OUTC];
__device__ float g_s[BB * NBR * OUTC];
__device__ float g_a1[CIN], g_b1[CIN], g_a2[BNC], g_b2[BNC];

// ---------------------------------------------------------------------------
// Kernel 0: fold BN params into scale/bias
// ---------------------------------------------------------------------------
__global__ void prep_bn_kernel(const float* __restrict__ g1, const float* __restrict__ be1,
                               const float* __restrict__ m1, const float* __restrict__ v1,
                               const float* __restrict__ g2, const float* __restrict__ be2,
                               const float* __restrict__ m2, const float* __restrict__ v2)
{
    int i = threadIdx.x;
    if (i < CIN) {
        float inv = g1[i] * rsqrtf(v1[i] + 1e-5f);
        g_a1[i] = inv;
        g_b1[i] = be1[i] - m1[i] * inv;
    }
    if (i < BNC) {
        float inv = g2[i] * rsqrtf(v2[i] + 1e-5f);
        g_a2[i] = inv;
        g_b2[i] = be2[i] - m2[i] * inv;
    }
}

// ---------------------------------------------------------------------------
// Kernel 1: h2[b,o,t] = relu(a2[o]*(sum_c W1[o,c]*relu(a1[c]*x[b,c,t]+b1[c]))+b2[o])
// Tiled GEMM: 64(o) x 64(t) block tile, BK=16, 256 threads, 4x4 per thread
// ---------------------------------------------------------------------------
__global__ __launch_bounds__(256)
void gemm_bn_kernel(const float* __restrict__ x, const float* __restrict__ W1)
{
    __shared__ float As[16][68];   // As[kk][o_in_tile]  (W1 transposed tile)
    __shared__ float Bs[16][68];   // Bs[kk][t_in_tile]  (bn-relu'd x tile)

    const int t0 = blockIdx.x * 64;
    const int om = blockIdx.y * 64;
    const int b  = blockIdx.z;

    const int tid = threadIdx.x;
    const int tx = tid & 15;       // t quad
    const int ty = tid >> 4;       // o quad

    float acc[4][4];
    #pragma unroll
    for (int i = 0; i < 4; i++)
        #pragma unroll
        for (int j = 0; j < 4; j++) acc[i][j] = 0.f;

    // loader decomposition
    const int arow = tid >> 2;          // 0..63 (o)
    const int acg  = tid & 3;           // c group of 4
    const int bkk  = tid >> 4;          // 0..15 (c)
    const int btg  = tid & 15;          // t group of 4

    for (int ck = 0; ck < CIN; ck += 16) {
        // A tile: W1[om+arow, ck + acg*4 .. +3]
        {
            float4 w = *reinterpret_cast<const float4*>(&W1[(om + arow) * CIN + ck + acg * 4]);
            As[acg * 4 + 0][arow] = w.x;
            As[acg * 4 + 1][arow] = w.y;
            As[acg * 4 + 2][arow] = w.z;
            As[acg * 4 + 3][arow] = w.w;
        }
        // B tile: bn-relu(x[b, ck+bkk, t0 + btg*4 .. +3])
        {
            int c = ck + bkk;
            int t = t0 + btg * 4;
            float a = g_a1[c], bb = g_b1[c];
            float4 v = make_float4(0.f, 0.f, 0.f, 0.f);
            if (t < TT)
                v = *reinterpret_cast<const float4*>(&x[((long)b * CIN + c) * TT + t]);
            Bs[bkk][btg * 4 + 0] = fmaxf(fmaf(v.x, a, bb), 0.f);
            Bs[bkk][btg * 4 + 1] = fmaxf(fmaf(v.y, a, bb), 0.f);
            Bs[bkk][btg * 4 + 2] = fmaxf(fmaf(v.z, a, bb), 0.f);
            Bs[bkk][btg * 4 + 3] = fmaxf(fmaf(v.w, a, bb), 0.f);
        }
        __syncthreads();

        #pragma unroll
        for (int kk = 0; kk < 16; kk++) {
            float4 af = *reinterpret_cast<const float4*>(&As[kk][ty * 4]);
            float4 bf = *reinterpret_cast<const float4*>(&Bs[kk][tx * 4]);
            float ar[4] = {af.x, af.y, af.z, af.w};
            float br[4] = {bf.x, bf.y, bf.z, bf.w};
            #pragma unroll
            for (int i = 0; i < 4; i++)
                #pragma unroll
                for (int j = 0; j < 4; j++)
                    acc[i][j] = fmaf(ar[i], br[j], acc[i][j]);
        }
        __syncthreads();
    }

    // epilogue: bn2 + relu, store h2
    const int tbase = t0 + tx * 4;
    if (tbase < TT) {
        #pragma unroll
        for (int i = 0; i < 4; i++) {
            int o = om + ty * 4 + i;
            float a = g_a2[o], bb = g_b2[o];
            float4 r;
            r.x = fmaxf(fmaf(acc[i][0], a, bb), 0.f);
            r.y = fmaxf(fmaf(acc[i][1], a, bb), 0.f);
            r.z = fmaxf(fmaf(acc[i][2], a, bb), 0.f);
            r.w = fmaxf(fmaf(acc[i][3], a, bb), 0.f);
            *reinterpret_cast<float4*>(&g_h2[((long)b * BNC + o) * TT + tbase]) = r;
        }
    }
}

// ---------------------------------------------------------------------------
// Kernel 2: dilated 3-branch conv. f[i,b,o,t] = sum_c sum_k w[i,o,c,k]*h2[b,c,t+(k-1)*(i+1)]
// 64(o) x 64(t) tile, BK=16, 256 threads, per thread 4(o)x4(t) per branch.
// ---------------------------------------------------------------------------
__global__ __launch_bounds__(256)
void conv_kernel(const float* __restrict__ conv_w)
{
    __shared__ float Hs[16][72];           // Hs[kk][p], p covers t0-3 .. t0+66
    __shared__ float Ws[3][3][16][64];     // Ws[branch][tap][kk][o_in_tile]

    const int t0 = blockIdx.x * 64;
    const int om = blockIdx.y * 64;
    const int b  = blockIdx.z;

    const int tid = threadIdx.x;
    const int tx = tid & 15;
    const int ty = tid >> 4;
    const int tb = tx * 4;         // thread t base within tile
    const int ob = ty * 4;         // thread o base within tile

    float acc[3][4][4];
    #pragma unroll
    for (int i = 0; i < 3; i++)
        #pragma unroll
        for (int oo = 0; oo < 4; oo++)
            #pragma unroll
            for (int t = 0; t < 4; t++) acc[i][oo][t] = 0.f;

    for (int ck = 0; ck < BNC; ck += 16) {
        // h tile with halo (+-3), zero padded
        for (int idx = tid; idx < 16 * 70; idx += 256) {
            int kk = idx / 70;
            int p  = idx % 70;
            int t  = t0 + p - 3;
            float v = 0.f;
            if (t >= 0 && t < TT)
                v = g_h2[((long)b * BNC + ck + kk) * TT + t];
            Hs[kk][p] = v;
        }
        // weight tiles: 3 branches x 3 taps x 16 c x 64 o
        for (int idx = tid; idx < 9216; idx += 256) {
            int i  = idx / 3072;
            int r  = idx - i * 3072;
            int mm = r / 48;
            int r2 = r - mm * 48;
            int kk = r2 / 3;
            int k  = r2 - kk * 3;
            Ws[i][k][kk][mm] = conv_w[(((long)i * OUTC + om + mm) * BNC + ck + kk) * 3 + k];
        }
        __syncthreads();

        #pragma unroll 1
        for (int kk = 0; kk < 16; kk++) {
            float hreg[10];
            #pragma unroll
            for (int r = 0; r < 10; r++) hreg[r] = Hs[kk][tb + r];

            #pragma unroll
            for (int i = 0; i < 3; i++) {
                #pragma unroll
                for (int k = 0; k < 3; k++) {
                    float4 w = *reinterpret_cast<const float4*>(&Ws[i][k][kk][ob]);
                    const int off = (k - 1) * (i + 1) + 3;   // 0..6
                    #pragma unroll
                    for (int t = 0; t < 4; t++) {
                        float hv = hreg[t + off];
                        acc[i][0][t] = fmaf(w.x, hv, acc[i][0][t]);
                        acc[i][1][t] = fmaf(w.y, hv, acc[i][1][t]);
                        acc[i][2][t] = fmaf(w.z, hv, acc[i][2][t]);
                        acc[i][3][t] = fmaf(w.w, hv, acc[i][3][t]);
                    }
                }
            }
        }
        __syncthreads();
    }

    const int tbase = t0 + tb;
    if (tbase < TT) {
        #pragma unroll
        for (int i = 0; i < 3; i++) {
            #pragma unroll
            for (int oo = 0; oo < 4; oo++) {
                int o = om + ob + oo;
                float4 r = make_float4(acc[i][oo][0], acc[i][oo][1], acc[i][oo][2], acc[i][oo][3]);
                *reinterpret_cast<float4*>(&g_f[(long)i * FSZ + ((long)b * OUTC + o) * TT + tbase]) = r;
            }
        }
    }
}

// ---------------------------------------------------------------------------
// Kernel 3: per-(b,o) high-order stats over T of xs = f0+f1+f2
// ---------------------------------------------------------------------------
__global__ __launch_bounds__(256)
void stats_kernel()
{
    const int bo = blockIdx.x;                 // b*512 + o
    const long base = (long)bo * TT;
    const int tid = threadIdx.x;

    float s1 = 0.f, s2 = 0.f, s3 = 0.f, s4 = 0.f;
    for (int t = tid; t < TT; t += 256) {
        float v = g_f[base + t] + g_f[FSZ + base + t] + g_f[2L * FSZ + base + t];
        float v2 = v * v;
        s1 += v; s2 += v2; s3 += v2 * v; s4 += v2 * v2;
    }

    __shared__ float4 red[256];
    red[tid] = make_float4(s1, s2, s3, s4);
    __syncthreads();
    for (int s = 128; s > 0; s >>= 1) {
        if (tid < s) {
            float4 a = red[tid], c = red[tid + s];
            red[tid] = make_float4(a.x + c.x, a.y + c.y, a.z + c.z, a.w + c.w);
        }
        __syncthreads();
    }

    if (tid == 0) {
        float4 r = red[0];
        const float n = (float)TT;
        float m   = r.x / n;
        float ex2 = r.y / n, ex3 = r.z / n, ex4 = r.w / n;
        float var = (r.y - n * m * m) / (n - 1.0f);
        var = fmaxf(var, 0.f);
        float sd = sqrtf(var);
        float sc = fmaxf(sd, 0.01f);
        float m2 = m * m;
        float m3c = ex3 - 3.f * m * ex2 + 2.f * m * m2;
        float m4c = ex4 - 4.f * m * ex3 + 6.f * m2 * ex2 - 3.f * m2 * m2;
        int b = bo >> 9, o = bo & 511;
        float* st = g_stats + (long)b * (4 * OUTC);
        st[o]            = m;
        st[OUTC + o]     = sd;
        st[2 * OUTC + o] = m3c / (sc * sc * sc);
        st[3 * OUTC + o] = m4c / (sc * sc * sc * sc);
    }
}

// ---------------------------------------------------------------------------
// Kernel 4: selection MLP + softmax over branches -> g_s[b,i,o]
// One block per batch. Warp-cooperative dot products (coalesced weight reads).
// ---------------------------------------------------------------------------
__global__ __launch_bounds__(512)
void select_kernel(const float* __restrict__ sel_W1, const float* __restrict__ sel_b1,
                   const float* __restrict__ sel_W2, const float* __restrict__ sel_b2)
{
    const int b = blockIdx.x;
    const int tid = threadIdx.x;
    const int warp = tid >> 5, lane = tid & 31;

    __shared__ float sstats[4 * OUTC];   // 2048
    __shared__ float sz[OUTC];           // 512
    __shared__ float ssv[NBR * OUTC];    // 1536

    for (int i = tid; i < 4 * OUTC; i += 512)
        sstats[i] = g_stats[(long)b * (4 * OUTC) + i];
    __syncthreads();

    // z[r] = sel_b1[r] + stats . sel_W1[r,:]
    for (int r = warp; r < OUTC; r += 16) {
        float p = 0.f;
        for (int c = lane; c < 4 * OUTC; c += 32)
            p = fmaf(sel_W1[(long)r * (4 * OUTC) + c], sstats[c], p);
        p += __shfl_xor_sync(0xffffffff, p, 16);
        p += __shfl_xor_sync(0xffffffff, p, 8);
        p += __shfl_xor_sync(0xffffffff, p, 4);
        p += __shfl_xor_sync(0xffffffff, p, 2);
        p += __shfl_xor_sync(0xffffffff, p, 1);
        if (lane == 0) sz[r] = p + sel_b1[r];
    }
    __syncthreads();

    // sv[i,o] = sel_b2[i,o] + z . sel_W2[i,o,:]
    for (int idx = warp; idx < NBR * OUTC; idx += 16) {
        float p = 0.f;
        for (int c = lane; c < OUTC; c += 32)
            p = fmaf(sel_W2[(long)idx * OUTC + c], sz[c], p);
        p += __shfl_xor_sync(0xffffffff, p, 16);
        p += __shfl_xor_sync(0xffffffff, p, 8);
        p += __shfl_xor_sync(0xffffffff, p, 4);
        p += __shfl_xor_sync(0xffffffff, p, 2);
        p += __shfl_xor_sync(0xffffffff, p, 1);
        if (lane == 0) ssv[idx] = p + sel_b2[idx];
    }
    __syncthreads();

    // softmax over the 3 branches, store weights
    if (tid < OUTC) {
        float v0 = ssv[tid], v1 = ssv[OUTC + tid], v2 = ssv[2 * OUTC + tid];
        float mx = fmaxf(v0, fmaxf(v1, v2));
        float e0 = __expf(v0 - mx), e1 = __expf(v1 - mx), e2 = __expf(v2 - mx);
        float inv = 1.f / (e0 + e1 + e2);
        float* sp = g_s + (long)b * (NBR * OUTC);
        sp[tid]            = e0 * inv;
        sp[OUTC + tid]     = e1 * inv;
        sp[2 * OUTC + tid] = e2 * inv;
    }
}

// ---------------------------------------------------------------------------
// Kernel 5: out[b,o,t] = sum_i s[b,i,o] * f[i,b,o,t]   (float4 elementwise)
// ---------------------------------------------------------------------------
__global__ __launch_bounds__(256)
void combine_kernel(float* __restrict__ out)
{
    const int idx = blockIdx.x * 256 + threadIdx.x;   // < 4,096,000 float4s
    const int bo = idx / (TT / 4);
    const int t4 = idx - bo * (TT / 4);
    const int b = bo >> 9, o = bo & 511;

    const float* sp = g_s + (long)b * (NBR * OUTC);
    float s0 = sp[o], s1 = sp[OUTC + o], s2 = sp[2 * OUTC + o];

    const long base = (long)bo * TT + t4 * 4;
    float4 f0 = *reinterpret_cast<const float4*>(g_f + base);
    float4 f1 = *reinterpret_cast<const float4*>(g_f + FSZ + base);
    float4 f2 = *reinterpret_cast<const float4*>(g_f + 2L * FSZ + base);
    float4 r;
    r.x = s0 * f0.x + s1 * f1.x + s2 * f2.x;
    r.y = s0 * f0.y + s1 * f1.y + s2 * f2.y;
    r.z = s0 * f0.z + s1 * f1.z + s2 * f2.z;
    r.w = s0 * f0.w + s1 * f1.w + s2 * f2.w;
    *reinterpret_cast<float4*>(out + base) = r;
}

// ---------------------------------------------------------------------------
extern "C" void kernel_launch(void* const* d_in, const int* in_sizes, int n_in,
                              void* d_out, int out_size)
{
    const float* x         = (const float*)d_in[0];
    const float* bn1_gamma = (const float*)d_in[1];
    const float* bn1_beta  = (const float*)d_in[2];
    const float* bn1_mean  = (const float*)d_in[3];
    const float* bn1_var   = (const float*)d_in[4];
    const float* W1        = (const float*)d_in[5];
    const float* bn2_gamma = (const float*)d_in[6];
    const float* bn2_beta  = (const float*)d_in[7];
    const float* bn2_mean  = (const float*)d_in[8];
    const float* bn2_var   = (const float*)d_in[9];
    const float* conv_w    = (const float*)d_in[10];
    const float* sel_W1    = (const float*)d_in[11];
    const float* sel_b1    = (const float*)d_in[12];
    const float* sel_W2    = (const float*)d_in[13];
    const float* sel_b2    = (const float*)d_in[14];
    float* out = (float*)d_out;

    prep_bn_kernel<<<1, 1024>>>(bn1_gamma, bn1_beta, bn1_mean, bn1_var,
                                bn2_gamma, bn2_beta, bn2_mean, bn2_var);

    dim3 ggrid((TT + 63) / 64, OUTC / 64, BB);     // 32 x 8 x 16
    gemm_bn_kernel<<<ggrid, 256>>>(x, W1);

    conv_kernel<<<ggrid, 256>>>(conv_w);

    stats_kernel<<<BB * OUTC, 256>>>();

    select_kernel<<<BB, 512>>>(sel_W1, sel_b1, sel_W2, sel_b2);

    combine_kernel<<<(BB * OUTC * TT / 4 + 255) / 256, 256>>>(out);
}

// round 2
// speedup vs baseline: 3.2812x; 3.2812x over previous
#include <cuda_runtime.h>
#include <cuda_bf16.h>
#include <stdint.h>

// Problem constants
#define BB   16
#define CIN  1024
#define TT   2000
#define BNC  512
#define OUTC 512
#define NBR  3
#define FSZ  (BB * OUTC * TT)            // 16,384,000 per branch
#define H2PLANE ((long)BB * BNC * TT)    // bf16 elements per split plane

// Scratch (device globals)
__device__ float g_f[NBR * FSZ];                       // 196.6 MB fp32 branch outputs
__device__ __nv_bfloat16 g_h2p[2L * BB * BNC * TT];    // hi/lo planes, [s][b][c][t]
__device__ uint32_t g_w1p[2 * 512 * 512];              // [s][c2][o] bf16-pairs of W1
__device__ uint32_t g_wcp[9 * 2 * 256 * 512];          // [(i,k)][s][c2][o] pairs of conv_w
__device__ float g_stats[BB * 4 * OUTC];
__device__ float g_s[BB * NBR * OUTC];
__device__ float g_a1[CIN], g_b1[CIN], g_a2[BNC], g_b2[BNC];

// ---------------------------------------------------------------------------
__device__ __forceinline__ uint32_t pack2(__nv_bfloat16 a, __nv_bfloat16 b) {
    return (uint32_t)__bfloat16_as_ushort(a) | ((uint32_t)__bfloat16_as_ushort(b) << 16);
}

__device__ __forceinline__ void split_bf16(float v, __nv_bfloat16& hi, __nv_bfloat16& lo) {
    hi = __float2bfloat16_rn(v);
    lo = __float2bfloat16_rn(v - __bfloat162float(hi));
}

__device__ __forceinline__ void mma16816(float* d, const uint32_t* a, const uint32_t* b) {
    asm volatile(
        "mma.sync.aligned.m16n8k16.row.col.f32.bf16.bf16.f32 "
        "{%0,%1,%2,%3}, {%4,%5,%6,%7}, {%8,%9}, {%0,%1,%2,%3};\n"
        : "+f"(d[0]), "+f"(d[1]), "+f"(d[2]), "+f"(d[3])
        : "r"(a[0]), "r"(a[1]), "r"(a[2]), "r"(a[3]), "r"(b[0]), "r"(b[1]));
}

// ---------------------------------------------------------------------------
// Kernel 0: fold BN params
// ---------------------------------------------------------------------------
__global__ void prep_bn_kernel(const float* __restrict__ g1, const float* __restrict__ be1,
                               const float* __restrict__ m1, const float* __restrict__ v1,
                               const float* __restrict__ g2, const float* __restrict__ be2,
                               const float* __restrict__ m2, const float* __restrict__ v2)
{
    int i = threadIdx.x;
    if (i < CIN) {
        float inv = g1[i] * rsqrtf(v1[i] + 1e-5f);
        g_a1[i] = inv;
        g_b1[i] = be1[i] - m1[i] * inv;
    }
    if (i < BNC) {
        float inv = g2[i] * rsqrtf(v2[i] + 1e-5f);
        g_a2[i] = inv;
        g_b2[i] = be2[i] - m2[i] * inv;
    }
}

// ---------------------------------------------------------------------------
// Kernel 0b: split W1 into bf16 hi/lo pair-packed layout [s][c2][o]
// ---------------------------------------------------------------------------
__global__ void prep_w1_kernel(const float* __restrict__ W1)
{
    int idx = blockIdx.x * 256 + threadIdx.x;
    if (idx >= 512 * 512) return;
    int o  = idx >> 9;
    int c2 = idx & 511;
    float w0 = W1[o * CIN + 2 * c2];
    float w1 = W1[o * CIN + 2 * c2 + 1];
    __nv_bfloat16 h0, l0, h1, l1;
    split_bf16(w0, h0, l0);
    split_bf16(w1, h1, l1);
    g_w1p[(0 * 512 + c2) * 512 + o] = pack2(h0, h1);
    g_w1p[(1 * 512 + c2) * 512 + o] = pack2(l0, l1);
}

// ---------------------------------------------------------------------------
// Kernel 0c: split conv_w into [(i*3+k)][s][c2][o] pair-packed layout
// conv_w layout: [i][o][c][k]
// ---------------------------------------------------------------------------
__global__ void prep_wc_kernel(const float* __restrict__ conv_w)
{
    int idx = blockIdx.x * 256 + threadIdx.x;     // 9*512*256
    if (idx >= 9 * 512 * 256) return;
    int comb = idx / (512 * 256);
    int r = idx - comb * (512 * 256);
    int o  = r >> 8;
    int c2 = r & 255;
    int i = comb / 3, k = comb % 3;
    const float* wp = conv_w + (((long)i * 512 + o) * 512) * 3 + k;
    float w0 = wp[(2 * c2) * 3];
    float w1 = wp[(2 * c2 + 1) * 3];
    __nv_bfloat16 h0, l0, h1, l1;
    split_bf16(w0, h0, l0);
    split_bf16(w1, h1, l1);
    g_wcp[((comb * 2 + 0) * 256 + c2) * 512 + o] = pack2(h0, h1);
    g_wcp[((comb * 2 + 1) * 256 + c2) * 512 + o] = pack2(l0, l1);
}

// ---------------------------------------------------------------------------
// Kernel 1: GEMM via bf16-split mma: h2 = relu(bn2(W1 @ relu(bn1(x))))
// tile 64(o) x 64(t), K-chunk 16, 8 warps (4o x 2t), warp: 16o x 32t
// ---------------------------------------------------------------------------
__global__ __launch_bounds__(256)
void gemm_mma_kernel(const float* __restrict__ x)
{
    __shared__ uint32_t As[2][8][72];    // [s][c2][o+pad]
    __shared__ uint32_t Bs[2][64][12];   // [s][t][c2+pad]

    const int t0 = blockIdx.x * 64;
    const int om = blockIdx.y * 64;
    const int b  = blockIdx.z;

    const int tid  = threadIdx.x;
    const int warp = tid >> 5, lane = tid & 31;
    const int g  = lane >> 2, tq = lane & 3;
    const int osub = (warp & 3) * 16;
    const int tsub = (warp >> 2) * 32;

    float acc[4][4];
    #pragma unroll
    for (int n = 0; n < 4; n++)
        #pragma unroll
        for (int j = 0; j < 4; j++) acc[n][j] = 0.f;

    const uint4* w1p4 = reinterpret_cast<const uint4*>(g_w1p);

    for (int ch = 0; ch < CIN / 16; ch++) {
        const int c0  = ch * 16;
        const int c2b = ch * 8;
        // A tile fill (uint4 copies)
        {
            int idx = tid;   // exactly 256
            int s   = idx >> 7;
            int r   = idx & 127;
            int c2l = r >> 4;
            int oq  = r & 15;
            uint4 v = w1p4[(((s * 512) + c2b + c2l) * 512 + om + oq * 4) >> 2];
            *reinterpret_cast<uint4*>(&As[s][c2l][oq * 4]) = v;
        }
        // B tile fill: bn1+relu then split
        #pragma unroll
        for (int rep = 0; rep < 2; rep++) {
            int idx = tid + rep * 256;           // < 512
            int c2l = idx >> 6;
            int tl  = idx & 63;
            int c   = c0 + 2 * c2l;
            int t   = t0 + tl;
            float v0 = 0.f, v1 = 0.f;
            if (t < TT) {
                v0 = fmaxf(fmaf(x[((long)b * CIN + c) * TT + t], g_a1[c], g_b1[c]), 0.f);
                v1 = fmaxf(fmaf(x[((long)b * CIN + c + 1) * TT + t], g_a1[c + 1], g_b1[c + 1]), 0.f);
            }
            __nv_bfloat16 h0, l0, h1, l1;
            split_bf16(v0, h0, l0);
            split_bf16(v1, h1, l1);
            Bs[0][tl][c2l] = pack2(h0, h1);
            Bs[1][tl][c2l] = pack2(l0, l1);
        }
        __syncthreads();

        uint32_t ah[4], al[4];
        ah[0] = As[0][tq][osub + g];     ah[1] = As[0][tq][osub + g + 8];
        ah[2] = As[0][tq + 4][osub + g]; ah[3] = As[0][tq + 4][osub + g + 8];
        al[0] = As[1][tq][osub + g];     al[1] = As[1][tq][osub + g + 8];
        al[2] = As[1][tq + 4][osub + g]; al[3] = As[1][tq + 4][osub + g + 8];

        #pragma unroll
        for (int nt = 0; nt < 4; nt++) {
            int brow = tsub + nt * 8 + g;
            uint32_t bh[2], bl[2];
            bh[0] = Bs[0][brow][tq]; bh[1] = Bs[0][brow][tq + 4];
            bl[0] = Bs[1][brow][tq]; bl[1] = Bs[1][brow][tq + 4];
            mma16816(acc[nt], ah, bh);
            mma16816(acc[nt], ah, bl);
            mma16816(acc[nt], al, bh);
        }
        __syncthreads();
    }

    // epilogue: bn2 + relu, split, store both planes
    uint32_t* h2u = reinterpret_cast<uint32_t*>(g_h2p);
    #pragma unroll
    for (int nt = 0; nt < 4; nt++) {
        int tb = t0 + tsub + nt * 8 + 2 * tq;
        if (tb < TT) {
            #pragma unroll
            for (int rh = 0; rh < 2; rh++) {
                int o = om + osub + g + 8 * rh;
                float av = g_a2[o], bv = g_b2[o];
                float w0 = fmaxf(fmaf(acc[nt][2 * rh], av, bv), 0.f);
                float w1 = fmaxf(fmaf(acc[nt][2 * rh + 1], av, bv), 0.f);
                __nv_bfloat16 h0, l0, h1, l1;
                split_bf16(w0, h0, l0);
                split_bf16(w1, h1, l1);
                long off = (((long)b * BNC + o) * TT + tb) >> 1;
                h2u[off]                      = pack2(h0, h1);
                h2u[off + (H2PLANE >> 1)]     = pack2(l0, l1);
            }
        }
    }
}

// ---------------------------------------------------------------------------
// Kernel 2: 3-branch dilated conv via bf16-split mma.
// tile 64(o) x 64(t), K-chunk 16c, 9 (branch,tap) A-matrices vs shared
// halo'd B tile; tap shift = B fragment row offset.
// ---------------------------------------------------------------------------
__global__ __launch_bounds__(256, 2)
void conv_mma_kernel()
{
    __shared__ uint32_t ws[9][2][8][72];   // [(i,k)][s][c2][o+pad]   41.5 KB
    __shared__ uint32_t hsp[2][70][12];    // [s][t(+halo)][c2+pad]    6.7 KB

    const int t0 = blockIdx.x * 64;
    const int om = blockIdx.y * 64;
    const int b  = blockIdx.z;

    const int tid  = threadIdx.x;
    const int warp = tid >> 5, lane = tid & 31;
    const int g  = lane >> 2, tq = lane & 3;
    const int osub = (warp & 3) * 16;
    const int tsub = (warp >> 2) * 32;

    float acc[3][4][4];
    #pragma unroll
    for (int i = 0; i < 3; i++)
        #pragma unroll
        for (int n = 0; n < 4; n++)
            #pragma unroll
            for (int j = 0; j < 4; j++) acc[i][n][j] = 0.f;

    const uint4* wcp4 = reinterpret_cast<const uint4*>(g_wcp);
    const __nv_bfloat16* h2 = g_h2p;

    for (int ch = 0; ch < BNC / 16; ch++) {
        const int c0  = ch * 16;
        const int c2b = ch * 8;
        // weight tiles (uint4 copies): 2304 uint4 per chunk
        #pragma unroll
        for (int rep = 0; rep < 9; rep++) {
            int idx  = tid + rep * 256;      // < 2304
            int comb = idx >> 8;
            int r    = idx & 255;
            int s    = r >> 7;
            int r2   = r & 127;
            int c2l  = r2 >> 4;
            int oq   = r2 & 15;
            uint4 v = wcp4[(((comb * 2 + s) * 256 + c2b + c2l) * 512 + om + oq * 4) >> 2];
            *reinterpret_cast<uint4*>(&ws[comb][s][c2l][oq * 4]) = v;
        }
        // h tile with halo: 560 pair-words per split
        for (int idx = tid; idx < 560; idx += 256) {
            int c2l = idx / 70;
            int tr  = idx - c2l * 70;
            int t   = t0 - 3 + tr;
            uint32_t vhi = 0, vlo = 0;
            if (t >= 0 && t < TT) {
                long p = ((long)b * BNC + c0 + 2 * c2l) * TT + t;
                vhi = pack2(h2[p], h2[p + TT]);
                vlo = pack2(h2[p + H2PLANE], h2[p + H2PLANE + TT]);
            }
            hsp[0][tr][c2l] = vhi;
            hsp[1][tr][c2l] = vlo;
        }
        __syncthreads();

        #pragma unroll
        for (int comb = 0; comb < 9; comb++) {
            const int br = comb / 3;
            const int k  = comb % 3;
            const int doff = (k - 1) * (br + 1) + 3;   // 0..6

            uint32_t ah[4], al[4];
            ah[0] = ws[comb][0][tq][osub + g];     ah[1] = ws[comb][0][tq][osub + g + 8];
            ah[2] = ws[comb][0][tq + 4][osub + g]; ah[3] = ws[comb][0][tq + 4][osub + g + 8];
            al[0] = ws[comb][1][tq][osub + g];     al[1] = ws[comb][1][tq][osub + g + 8];
            al[2] = ws[comb][1][tq + 4][osub + g]; al[3] = ws[comb][1][tq + 4][osub + g + 8];

            #pragma unroll
            for (int nt = 0; nt < 4; nt++) {
                int brow = tsub + nt * 8 + g + doff;
                uint32_t bh[2], bl[2];
                bh[0] = hsp[0][brow][tq]; bh[1] = hsp[0][brow][tq + 4];
                bl[0] = hsp[1][brow][tq]; bl[1] = hsp[1][brow][tq + 4];
                mma16816(acc[br][nt], ah, bh);
                mma16816(acc[br][nt], ah, bl);
                mma16816(acc[br][nt], al, bh);
            }
        }
        __syncthreads();
    }

    // epilogue: fp32 branch outputs
    #pragma unroll
    for (int br = 0; br < 3; br++) {
        #pragma unroll
        for (int nt = 0; nt < 4; nt++) {
            int tb = t0 + tsub + nt * 8 + 2 * tq;
            if (tb < TT) {
                long base = (long)br * FSZ + ((long)b * OUTC + om + osub + g) * TT + tb;
                *reinterpret_cast<float2*>(&g_f[base]) =
                    make_float2(acc[br][nt][0], acc[br][nt][1]);
                *reinterpret_cast<float2*>(&g_f[base + 8L * TT]) =
                    make_float2(acc[br][nt][2], acc[br][nt][3]);
            }
        }
    }
}

// ---------------------------------------------------------------------------
// Kernel 3: per-(b,o) high-order stats over T of xs = f0+f1+f2
// ---------------------------------------------------------------------------
__global__ __launch_bounds__(256)
void stats_kernel()
{
    const int bo = blockIdx.x;
    const long base = (long)bo * TT;
    const int tid = threadIdx.x;

    float s1 = 0.f, s2 = 0.f, s3 = 0.f, s4 = 0.f;
    for (int t = tid; t < TT; t += 256) {
        float v = g_f[base + t] + g_f[FSZ + base + t] + g_f[2L * FSZ + base + t];
        float v2 = v * v;
        s1 += v; s2 += v2; s3 += v2 * v; s4 += v2 * v2;
    }

    __shared__ float4 red[256];
    red[tid] = make_float4(s1, s2, s3, s4);
    __syncthreads();
    for (int s = 128; s > 0; s >>= 1) {
        if (tid < s) {
            float4 a = red[tid], c = red[tid + s];
            red[tid] = make_float4(a.x + c.x, a.y + c.y, a.z + c.z, a.w + c.w);
        }
        __syncthreads();
    }

    if (tid == 0) {
        float4 r = red[0];
        const float n = (float)TT;
        float m   = r.x / n;
        float ex2 = r.y / n, ex3 = r.z / n, ex4 = r.w / n;
        float var = (r.y - n * m * m) / (n - 1.0f);
        var = fmaxf(var, 0.f);
        float sd = sqrtf(var);
        float sc = fmaxf(sd, 0.01f);
        float m2 = m * m;
        float m3c = ex3 - 3.f * m * ex2 + 2.f * m * m2;
        float m4c = ex4 - 4.f * m * ex3 + 6.f * m2 * ex2 - 3.f * m2 * m2;
        int b = bo >> 9, o = bo & 511;
        float* st = g_stats + (long)b * (4 * OUTC);
        st[o]            = m;
        st[OUTC + o]     = sd;
        st[2 * OUTC + o] = m3c / (sc * sc * sc);
        st[3 * OUTC + o] = m4c / (sc * sc * sc * sc);
    }
}

// ---------------------------------------------------------------------------
// Kernel 4: selection MLP + softmax over branches -> g_s[b,i,o]
// ---------------------------------------------------------------------------
__global__ __launch_bounds__(512)
void select_kernel(const float* __restrict__ sel_W1, const float* __restrict__ sel_b1,
                   const float* __restrict__ sel_W2, const float* __restrict__ sel_b2)
{
    const int b = blockIdx.x;
    const int tid = threadIdx.x;
    const int warp = tid >> 5, lane = tid & 31;

    __shared__ float sstats[4 * OUTC];
    __shared__ float sz[OUTC];
    __shared__ float ssv[NBR * OUTC];

    for (int i = tid; i < 4 * OUTC; i += 512)
        sstats[i] = g_stats[(long)b * (4 * OUTC) + i];
    __syncthreads();

    for (int r = warp; r < OUTC; r += 16) {
        float p = 0.f;
        for (int c = lane; c < 4 * OUTC; c += 32)
            p = fmaf(sel_W1[(long)r * (4 * OUTC) + c], sstats[c], p);
        p += __shfl_xor_sync(0xffffffff, p, 16);
        p += __shfl_xor_sync(0xffffffff, p, 8);
        p += __shfl_xor_sync(0xffffffff, p, 4);
        p += __shfl_xor_sync(0xffffffff, p, 2);
        p += __shfl_xor_sync(0xffffffff, p, 1);
        if (lane == 0) sz[r] = p + sel_b1[r];
    }
    __syncthreads();

    for (int idx = warp; idx < NBR * OUTC; idx += 16) {
        float p = 0.f;
        for (int c = lane; c < OUTC; c += 32)
            p = fmaf(sel_W2[(long)idx * OUTC + c], sz[c], p);
        p += __shfl_xor_sync(0xffffffff, p, 16);
        p += __shfl_xor_sync(0xffffffff, p, 8);
        p += __shfl_xor_sync(0xffffffff, p, 4);
        p += __shfl_xor_sync(0xffffffff, p, 2);
        p += __shfl_xor_sync(0xffffffff, p, 1);
        if (lane == 0) ssv[idx] = p + sel_b2[idx];
    }
    __syncthreads();

    if (tid < OUTC) {
        float v0 = ssv[tid], v1 = ssv[OUTC + tid], v2 = ssv[2 * OUTC + tid];
        float mx = fmaxf(v0, fmaxf(v1, v2));
        float e0 = __expf(v0 - mx), e1 = __expf(v1 - mx), e2 = __expf(v2 - mx);
        float inv = 1.f / (e0 + e1 + e2);
        float* sp = g_s + (long)b * (NBR * OUTC);
        sp[tid]            = e0 * inv;
        sp[OUTC + tid]     = e1 * inv;
        sp[2 * OUTC + tid] = e2 * inv;
    }
}

// ---------------------------------------------------------------------------
// Kernel 5: out[b,o,t] = sum_i s[b,i,o] * f[i,b,o,t]
// ---------------------------------------------------------------------------
__global__ __launch_bounds__(256)
void combine_kernel(float* __restrict__ out)
{
    const int idx = blockIdx.x * 256 + threadIdx.x;
    const int bo = idx / (TT / 4);
    const int t4 = idx - bo * (TT / 4);
    const int b = bo >> 9, o = bo & 511;

    const float* sp = g_s + (long)b * (NBR * OUTC);
    float s0 = sp[o], s1 = sp[OUTC + o], s2 = sp[2 * OUTC + o];

    const long base = (long)bo * TT + t4 * 4;
    float4 f0 = *reinterpret_cast<const float4*>(g_f + base);
    float4 f1 = *reinterpret_cast<const float4*>(g_f + FSZ + base);
    float4 f2 = *reinterpret_cast<const float4*>(g_f + 2L * FSZ + base);
    float4 r;
    r.x = s0 * f0.x + s1 * f1.x + s2 * f2.x;
    r.y = s0 * f0.y + s1 * f1.y + s2 * f2.y;
    r.z = s0 * f0.z + s1 * f1.z + s2 * f2.z;
    r.w = s0 * f0.w + s1 * f1.w + s2 * f2.w;
    *reinterpret_cast<float4*>(out + base) = r;
}

// ---------------------------------------------------------------------------
extern "C" void kernel_launch(void* const* d_in, const int* in_sizes, int n_in,
                              void* d_out, int out_size)
{
    const float* x         = (const float*)d_in[0];
    const float* bn1_gamma = (const float*)d_in[1];
    const float* bn1_beta  = (const float*)d_in[2];
    const float* bn1_mean  = (const float*)d_in[3];
    const float* bn1_var   = (const float*)d_in[4];
    const float* W1        = (const float*)d_in[5];
    const float* bn2_gamma = (const float*)d_in[6];
    const float* bn2_beta  = (const float*)d_in[7];
    const float* bn2_mean  = (const float*)d_in[8];
    const float* bn2_var   = (const float*)d_in[9];
    const float* conv_w    = (const float*)d_in[10];
    const float* sel_W1    = (const float*)d_in[11];
    const float* sel_b1    = (const float*)d_in[12];
    const float* sel_W2    = (const float*)d_in[13];
    const float* sel_b2    = (const float*)d_in[14];
    float* out = (float*)d_out;

    prep_bn_kernel<<<1, 1024>>>(bn1_gamma, bn1_beta, bn1_mean, bn1_var,
                                bn2_gamma, bn2_beta, bn2_mean, bn2_var);
    prep_w1_kernel<<<(512 * 512 + 255) / 256, 256>>>(W1);
    prep_wc_kernel<<<(9 * 512 * 256 + 255) / 256, 256>>>(conv_w);

    dim3 grid((TT + 63) / 64, OUTC / 64, BB);   // 32 x 8 x 16
    gemm_mma_kernel<<<grid, 256>>>(x);
    conv_mma_kernel<<<grid, 256>>>();

    stats_kernel<<<BB * OUTC, 256>>>();
    select_kernel<<<BB, 512>>>(sel_W1, sel_b1, sel_W2, sel_b2);
    combine_kernel<<<(BB * OUTC * TT / 4 + 255) / 256, 256>>>(out);
}